// round 7
// baseline (speedup 1.0000x reference)
#include <cuda_runtime.h>
#include <cuda_bf16.h>

// Encoder_57380763074770: batched GRU cell — fully fused single kernel.
// Inputs (metadata order):
//  0: x [64,17] f32   1: ip [64,8] i32      2: port [64,2] i32
//  3: hidden [1,1,128] 4: ip_emb [256,1]    5: port_emb [70000,4]
//  6: W_ih [384,33]    7: W_hh [384,128]    8: b_ih [384]   9: b_hh [384]
// Output 0: outputs [64,128] f32
// Output 1: new_hidden [128] f32 = outputs[63], at offset 64*128

#define H 128
#define FIN 33
#define STEPS 64
#define GH_BLOCKS 32           // 32 blocks x 12 warps = 384 rows (one warp per row)
#define NTHREADS 384

// Scratch + handshake state (device globals; zero-initialized at load).
__device__ float g_gh[3 * H];
__device__ int   g_count;      // # gh blocks finished (reset to 0 each run)
__device__ int   g_done;       // # step blocks finished (reset to 0 each run)

__global__ void __launch_bounds__(NTHREADS, 1)
fused_kernel(const float* __restrict__ x,
             const int*   __restrict__ ip,
             const int*   __restrict__ port,
             const float* __restrict__ hidden,
             const float* __restrict__ ip_emb,
             const float* __restrict__ port_emb,
             const float* __restrict__ W_ih,
             const float* __restrict__ W_hh,
             const float* __restrict__ b_ih,
             const float* __restrict__ b_hh,
             float* __restrict__ out,
             int out_size)
{
    const int t    = threadIdx.x;
    const int lane = t & 31;
    const int warp = t >> 5;

    if (blockIdx.x < GH_BLOCKS) {
        // ======== producer: gh[j] = h0 . W_hh[j] + b_hh[j], one warp per row ====
        const int j = blockIdx.x * 12 + warp;              // 0..383
        const float4 hv = reinterpret_cast<const float4*>(hidden)[lane];
        const float4 wv = reinterpret_cast<const float4*>(W_hh + j * H)[lane];
        float p = hv.x * wv.x + hv.y * wv.y + hv.z * wv.z + hv.w * wv.w;
        #pragma unroll
        for (int off = 16; off > 0; off >>= 1)
            p += __shfl_down_sync(0xffffffffu, p, off);
        if (lane == 0) g_gh[j] = p + b_hh[j];

        __threadfence();                                   // publish g_gh
        __syncthreads();                                   // all 12 rows written
        if (t == 0) atomicAdd(&g_count, 1);
        return;
    }

    // ======== consumer: one block per step ================================
    const int s = blockIdx.x - GH_BLOCKS;                  // 0..63

    __shared__ float s_xi[36];
    __shared__ float s_gi[3 * H];

    // xi[33] = concat(x[s], ip_emb[ip[s]], port_emb[port[s]])
    if (t < 17) {
        s_xi[t] = x[s * 17 + t];
    } else if (t < 25) {
        s_xi[t] = ip_emb[ip[s * 8 + (t - 17)]];            // ip_emb dim=1
    } else if (t < 33) {
        int q = t - 25;
        s_xi[t] = port_emb[port[s * 2 + (q >> 2)] * 4 + (q & 3)];
    }
    __syncthreads();

    // gi[t] = xi . W_ih[t] + b_ih[t]  — one thread per row, coalesced across warp
    {
        float a = b_ih[t];
        const float* wr = W_ih + t * FIN;
        #pragma unroll
        for (int k = 0; k < FIN; k++)
            a = fmaf(s_xi[k], wr[k], a);                   // LDS broadcast + LDG
        s_gi[t] = a;
    }

    // Wait for gh (overlapped with the gi work above).
    if (t == 0) {
        while (*(volatile int*)&g_count < GH_BLOCKS) { }
        __threadfence();                                   // acquire
    }
    __syncthreads();

    // Gates: threads 0..127, one per hidden unit.
    if (t < H) {
        const float i_r = s_gi[t];
        const float i_z = s_gi[t + H];
        const float i_n = s_gi[t + 2 * H];
        const float h_r = __ldcg(&g_gh[t]);
        const float h_z = __ldcg(&g_gh[t + H]);
        const float h_n = __ldcg(&g_gh[t + 2 * H]);
        const float h0v = hidden[t];

        const float r = 1.0f / (1.0f + __expf(-(i_r + h_r)));
        const float z = 1.0f / (1.0f + __expf(-(i_z + h_z)));
        const float n = tanhf(i_n + r * h_n);
        const float o = (1.0f - z) * n + z * h0v;

        out[s * H + t] = o;
        if (s == STEPS - 1 && out_size >= STEPS * H + H)
            out[STEPS * H + t] = o;                        // new_hidden
    }

    // Self-clean for next graph replay: last step block resets the counters.
    __threadfence();
    __syncthreads();
    if (t == 0) {
        int prev = atomicAdd(&g_done, 1);
        if (prev == STEPS - 1) {
            *(volatile int*)&g_count = 0;
            *(volatile int*)&g_done  = 0;
        }
    }
}

extern "C" void kernel_launch(void* const* d_in, const int* in_sizes, int n_in,
                              void* d_out, int out_size)
{
    const float* x        = (const float*)d_in[0];
    const int*   ip       = (const int*)  d_in[1];
    const int*   port     = (const int*)  d_in[2];
    const float* hidden   = (const float*)d_in[3];
    const float* ip_emb   = (const float*)d_in[4];
    const float* port_emb = (const float*)d_in[5];
    const float* W_ih     = (const float*)d_in[6];
    const float* W_hh     = (const float*)d_in[7];
    const float* b_ih     = (const float*)d_in[8];
    const float* b_hh     = (const float*)d_in[9];

    fused_kernel<<<GH_BLOCKS + STEPS, NTHREADS>>>(
        x, ip, port, hidden, ip_emb, port_emb,
        W_ih, W_hh, b_ih, b_hh, (float*)d_out, out_size);
}